// round 7
// baseline (speedup 1.0000x reference)
#include <cuda_runtime.h>
#include <math.h>

// Problem constants (B=8, L=4096, D=1024, fp32)
#define BB 8
#define LL 4096
#define DD 1024
#define ND (LL - 1)   // 4095 deltas per batch row
#define NI (LL - 2)   // 4094 delta_increase terms per batch
#define TC 32         // loss terms per block; computes TC+1 deltas from TC+2 rows

// Accumulators. Zero-initialized at load; last block resets them each launch
// so graph replays are deterministic.
__device__ float g_ws;
__device__ float g_ms;
__device__ unsigned int g_ticket;

__device__ __forceinline__ float sqnorm_diff(float4 a, float4 b) {
    float dx = a.x - b.x, dy = a.y - b.y, dz = a.z - b.z, dw = a.w - b.w;
    return fmaf(dx, dx, fmaf(dy, dy, fmaf(dz, dz, dw * dw)));
}

// 2-step partial reduce: after xor-16 and xor-8, lane l holds the sum over
// lanes {l, l^8, l^16, l^24}; lanes 0..7 hold the 8 distinct group sums.
__device__ __forceinline__ float pre_reduce8(float s) {
    s += __shfl_xor_sync(0xffffffffu, s, 16);
    s += __shfl_xor_sync(0xffffffffu, s, 8);
    return s;
}

// Fused kernel. Block (bx, b) owns loss terms t in [32*bx, 32*bx+32) ∩ [0,NI).
// Phase 1: stream 34 rows; per-delta 2-shfl pre-reduce, lanes 0..7 store into
//          s_part[i][warp*8+lane] (8.4 KB -> 7 CTAs/SM -> ONE wave of 1024).
// Phase 2: warp w reduces deltas i ≡ w (mod 8): 2 LDS + 5 SHFL, sqrt.
// Phase 3: warp 0 computes 32 weighted loss terms, one atomicAdd pair per
//          block; last block (ticket) publishes out and resets state.
//
// rtp dtype hedge: buffer may be int64 or int32. Read as 16 int32 words;
// little-endian int64 values < 4096 => all odd words zero => take even words.
__global__ __launch_bounds__(256, 7) void fused_kernel(const float* __restrict__ states,
                                                       const float* __restrict__ reasoning_mask,
                                                       const int* __restrict__ rtp_raw,
                                                       float* __restrict__ out) {
    const int b   = blockIdx.y;
    const int t0  = blockIdx.x * TC;
    const int tid = threadIdx.x;
    const int warp = tid >> 5;
    const int lane = tid & 31;
    const unsigned int nblocks = gridDim.x * gridDim.y;

    const float4* __restrict__ base =
        reinterpret_cast<const float4*>(states + (size_t)b * LL * DD);

    __shared__ float s_part[TC + 1][64];    // 8 group-sums per warp per delta
    __shared__ float delta_sm[TC + 1];

    const int sp_col = warp * 8 + lane;     // valid when lane < 8

    // ---- Phase 1: stream 34 rows, emit 33 pre-reduced partial rows ----
    if (t0 + TC + 1 < LL) {
        // Clean path: 8 chunks of 4 deltas + 1 tail delta.
        float4 prev = base[(size_t)t0 * 256 + tid];
        #pragma unroll
        for (int ch = 0; ch < 8; ch++) {
            const size_t r = (size_t)(t0 + 4 * ch + 1) * 256 + tid;
            float4 c0 = base[r];
            float4 c1 = base[r + 256];
            float4 c2 = base[r + 512];
            float4 c3 = base[r + 768];
            float s0 = pre_reduce8(sqnorm_diff(c0, prev));
            float s1 = pre_reduce8(sqnorm_diff(c1, c0));
            float s2 = pre_reduce8(sqnorm_diff(c2, c1));
            float s3 = pre_reduce8(sqnorm_diff(c3, c2));
            if (lane < 8) {
                s_part[4 * ch + 0][sp_col] = s0;
                s_part[4 * ch + 1][sp_col] = s1;
                s_part[4 * ch + 2][sp_col] = s2;
                s_part[4 * ch + 3][sp_col] = s3;
            }
            prev = c3;
        }
        float4 cl = base[(size_t)(t0 + TC + 1) * 256 + tid];
        float sl = pre_reduce8(sqnorm_diff(cl, prev));
        if (lane < 8) s_part[TC][sp_col] = sl;
    } else {
        // Guarded path (last x-block only).
        float4 prev = base[(size_t)t0 * 256 + tid];
        #pragma unroll
        for (int i = 0; i <= TC; i++) {
            const int t = t0 + i;
            float s = 0.0f;
            float4 cur = prev;
            if (t < ND) {
                cur = base[(size_t)(t + 1) * 256 + tid];
                s = sqnorm_diff(cur, prev);
            }
            s = pre_reduce8(s);
            if (lane < 8) s_part[i][sp_col] = s;
            prev = cur;
        }
    }

    __syncthreads();

    // ---- Phase 2: reduce 64 partials per delta. Warp w handles deltas
    //      i = w, w+8, ... <= TC (conflict-free LDS). ----
    for (int i = warp; i <= TC; i += 8) {
        float v = s_part[i][lane] + s_part[i][lane + 32];
        #pragma unroll
        for (int o = 16; o > 0; o >>= 1)
            v += __shfl_xor_sync(0xffffffffu, v, o);
        if (lane == 0) delta_sm[i] = sqrtf(v);
    }

    __syncthreads();

    // ---- Phase 3: loss terms, warp 0 only (32 terms, one per lane) ----
    if (warp == 0) {
        int odd_or = 0;
        #pragma unroll
        for (int i = 1; i < 16; i += 2) odd_or |= rtp_raw[i];
        const int rtp_b = (odd_or == 0) ? rtp_raw[2 * b] : rtp_raw[b];

        const int t = t0 + lane;          // term index
        float ws = 0.0f, ms = 0.0f;
        if (t < NI) {
            float di = fmaxf(delta_sm[lane + 1] - delta_sm[lane], 0.0f);
            const float m = reasoning_mask[b * LL + t + 2];
            int dist = rtp_b - t - 2;
            if (dist < 0) dist = 0;
            const float w = (dist < 5) ? (2.0f + (float)(5 - dist) * 0.5f) : 1.0f;
            ws = di * m * w;
            ms = m;
        }
        #pragma unroll
        for (int o = 16; o > 0; o >>= 1) {
            ws += __shfl_xor_sync(0xffffffffu, ws, o);
            ms += __shfl_xor_sync(0xffffffffu, ms, o);
        }
        if (lane == 0) {
            atomicAdd(&g_ws, ws);
            atomicAdd(&g_ms, ms);
            __threadfence();
            const unsigned int my = atomicAdd(&g_ticket, 1u);
            if (my == nblocks - 1u) {
                __threadfence();
                const float tws = *(volatile float*)&g_ws;
                const float tms = *(volatile float*)&g_ms;
                out[0] = tws / (tms + 1e-9f);
                // reset for next graph replay (all blocks done: safe)
                g_ws = 0.0f;
                g_ms = 0.0f;
                g_ticket = 0u;
            }
        }
    }
}

extern "C" void kernel_launch(void* const* d_in, const int* in_sizes, int n_in,
                              void* d_out, int out_size) {
    const float* states = (const float*)d_in[0];
    const float* rmask  = (const float*)d_in[1];
    const int*   rtp    = (const int*)d_in[2];
    float*       out    = (float*)d_out;

    dim3 grid((NI + TC - 1) / TC, BB);   // (128, 8) = 1024 blocks
    fused_kernel<<<grid, 256>>>(states, rmask, rtp, out);
}

// round 8
// speedup vs baseline: 1.0958x; 1.0958x over previous
#include <cuda_runtime.h>
#include <math.h>

// Problem constants (B=8, L=4096, D=1024, fp32)
#define BB 8
#define LL 4096
#define ND (LL - 1)       // 4095 deltas per batch
#define NI (LL - 2)       // 4094 loss terms per batch
#define TC 56             // terms per block
#define NDEL (TC + 1)     // 57 deltas per block
#define XBLK 74           // blocks per batch: 74*56 = 4144 >= 4094
// grid = (74, 8) = 592 = 148 SMs * 4 CTAs -> ONE perfectly balanced wave

// Accumulators. Zero-initialized at load; last block resets them each launch.
__device__ float g_ws;
__device__ float g_ms;
__device__ unsigned int g_ticket;

__device__ __forceinline__ float sqnorm_diff(float4 a, float4 b) {
    float dx = a.x - b.x, dy = a.y - b.y, dz = a.z - b.z, dw = a.w - b.w;
    return fmaf(dx, dx, fmaf(dy, dy, fmaf(dz, dz, dw * dw)));
}

// Fused kernel. Block (bx, b) owns terms t in [56*bx, 56*bx+56) ∩ [0, NI).
// Phase 1: stream 58 rows in chunks of 8 (8 LDG.128 in flight per thread,
//          64-reg budget at 4 CTAs/SM), ONE xor-16 shfl per delta, lanes
//          0..15 store into s_part[i][warp*16+lane]  (57 x 128, ~30 KB).
// Phase 2: warp w reduces deltas i ≡ w (mod 8): 4 LDS + 5 SHFL + sqrt.
// Phase 3: warp 0 computes the 56 weighted loss terms (2 per lane), one
//          atomicAdd pair per block; ticketed last block publishes + resets.
//
// rtp dtype hedge: buffer may be int64 or int32. Read as 16 int32 words;
// little-endian int64 values < 4096 => all odd words zero => take even words.
__global__ __launch_bounds__(256, 4) void fused_kernel(const float* __restrict__ states,
                                                       const float* __restrict__ reasoning_mask,
                                                       const int* __restrict__ rtp_raw,
                                                       float* __restrict__ out) {
    const int b   = blockIdx.y;
    const int t0  = blockIdx.x * TC;
    const int tid = threadIdx.x;
    const int warp = tid >> 5;
    const int lane = tid & 31;
    const unsigned int nblocks = gridDim.x * gridDim.y;

    const float4* __restrict__ base =
        reinterpret_cast<const float4*>(states + (size_t)b * LL * (size_t)1024);

    __shared__ float s_part[NDEL][128];    // 16 half-warp sums per warp-slot
    __shared__ float delta_sm[NDEL];

    const int sp_col = warp * 16 + lane;   // valid when lane < 16

    // ---- Phase 1: stream rows t0 .. t0+57, emit 57 pre-reduced partials ----
    if (t0 + NDEL <= LL - 1) {
        // Clean path: 7 chunks x 8 rows + 1 tail row.
        float4 prev = base[(size_t)t0 * 256 + tid];
        #pragma unroll
        for (int ch = 0; ch < 7; ch++) {
            const size_t r = (size_t)(t0 + 8 * ch + 1) * 256 + tid;
            float4 c[8];
            #pragma unroll
            for (int j = 0; j < 8; j++) c[j] = base[r + 256 * j];

            float s[8];
            s[0] = sqnorm_diff(c[0], prev);
            #pragma unroll
            for (int j = 1; j < 8; j++) s[j] = sqnorm_diff(c[j], c[j - 1]);

            #pragma unroll
            for (int j = 0; j < 8; j++) {
                float v = s[j] + __shfl_xor_sync(0xffffffffu, s[j], 16);
                if (lane < 16) s_part[8 * ch + j][sp_col] = v;
            }
            prev = c[7];
        }
        float4 cl = base[(size_t)(t0 + NDEL) * 256 + tid];
        float vl = sqnorm_diff(cl, prev);
        vl += __shfl_xor_sync(0xffffffffu, vl, 16);
        if (lane < 16) s_part[NDEL - 1][sp_col] = vl;
    } else {
        // Guarded path (last x-block only): clamp rows; out-of-range deltas
        // become 0 (diff of identical clamped rows) and are unused anyway.
        float4 prev = base[(size_t)t0 * 256 + tid];
        #pragma unroll 4
        for (int i = 0; i < NDEL; i++) {
            int row = t0 + i + 1;
            if (row > LL - 1) row = LL - 1;
            float4 cur = base[(size_t)row * 256 + tid];
            float v = sqnorm_diff(cur, prev);
            v += __shfl_xor_sync(0xffffffffu, v, 16);
            if (lane < 16) s_part[i][sp_col] = v;
            prev = cur;
        }
    }

    __syncthreads();

    // ---- Phase 2: reduce 128 partials per delta. Warp w handles deltas
    //      i = w, w+8, ... < NDEL (conflict-free LDS). ----
    for (int i = warp; i < NDEL; i += 8) {
        float v = s_part[i][lane] + s_part[i][lane + 32]
                + s_part[i][lane + 64] + s_part[i][lane + 96];
        #pragma unroll
        for (int o = 16; o > 0; o >>= 1)
            v += __shfl_xor_sync(0xffffffffu, v, o);
        if (lane == 0) delta_sm[i] = sqrtf(v);
    }

    __syncthreads();

    // ---- Phase 3: loss terms, warp 0 only (56 terms, 2 per lane) ----
    if (warp == 0) {
        int odd_or = 0;
        #pragma unroll
        for (int i = 1; i < 16; i += 2) odd_or |= rtp_raw[i];
        const int rtp_b = (odd_or == 0) ? rtp_raw[2 * b] : rtp_raw[b];

        float ws = 0.0f, ms = 0.0f;
        #pragma unroll
        for (int h = 0; h < 2; h++) {
            const int li = lane + 32 * h;     // local term index
            const int t = t0 + li;
            if (li < TC && t < NI) {
                float di = fmaxf(delta_sm[li + 1] - delta_sm[li], 0.0f);
                const float m = reasoning_mask[b * LL + t + 2];
                int dist = rtp_b - t - 2;
                if (dist < 0) dist = 0;
                const float w = (dist < 5) ? (2.0f + (float)(5 - dist) * 0.5f) : 1.0f;
                ws += di * m * w;
                ms += m;
            }
        }
        #pragma unroll
        for (int o = 16; o > 0; o >>= 1) {
            ws += __shfl_xor_sync(0xffffffffu, ws, o);
            ms += __shfl_xor_sync(0xffffffffu, ms, o);
        }
        if (lane == 0) {
            atomicAdd(&g_ws, ws);
            atomicAdd(&g_ms, ms);
            __threadfence();
            const unsigned int my = atomicAdd(&g_ticket, 1u);
            if (my == nblocks - 1u) {
                __threadfence();
                const float tws = *(volatile float*)&g_ws;
                const float tms = *(volatile float*)&g_ms;
                out[0] = tws / (tms + 1e-9f);
                // reset for next graph replay (all blocks done: safe)
                g_ws = 0.0f;
                g_ms = 0.0f;
                g_ticket = 0u;
            }
        }
    }
}

extern "C" void kernel_launch(void* const* d_in, const int* in_sizes, int n_in,
                              void* d_out, int out_size) {
    const float* states = (const float*)d_in[0];
    const float* rmask  = (const float*)d_in[1];
    const int*   rtp    = (const int*)d_in[2];
    float*       out    = (float*)d_out;

    dim3 grid(XBLK, BB);   // (74, 8) = 592 blocks = 148 SMs x 4
    fused_kernel<<<grid, 256>>>(states, rmask, rtp, out);
}